// round 14
// baseline (speedup 1.0000x reference)
#include <cuda_runtime.h>
#include <cstdint>

// ConstituencyMFVI: B=8, N=192, 3 mean-field iterations.
// q[b,i,j] = s_span[b,i,j] + (j>i) * sum_{k != i, k != j} sigmoid(q[b,i,k]) * s_pair[b,i,j,k]
// out = sigmoid(q).
//
// R14 == R13 resubmitted (previous round failed in harness device init --
// "system not yet initialized" -- before any kernel code ran).
//
// Design: direct-to-register LDG, no staging.
// cp.async tops out at ~3 TB/s (LDGSTS issue-rate floor); TMA is worse. So:
// 148 persistent CTAs x 384 threads; warp w owns rows 16w..16w+15; lane l
// holds P[j, l+32c] (c=0..5) in registers -> every LDG.32 warp-instruction
// touches exactly one 128B line (perfectly coalesced, 1 wavefront/inst),
// with ~96 outstanding loads/thread of MLP.
// Per iteration: lane reads sigma[l+32c] (conflict-free LDS), 3 packed
// fma.rn.f32x2 per row, 5-round butterfly reduces 16 row-partials (all lanes
// end with every row's sum -> combine lane u uses part[u] directly).
// Exclusions k==i / k==j subtracted at combine from 2 prefetched scalars.
// sigma double-buffered; 4 barriers/tile. L2-prefetch of tile n+1 hides the
// inter-tile demand miss. Rows j<=i never read: 113MB total HBM.

namespace {
constexpr int NN      = 192;
constexpr int NSM     = 148;
constexpr int THREADS = 384;     // 12 warps
constexpr int RPW     = 16;      // rows per warp
}

__device__ __forceinline__ float sigmoidf(float x) {
    return 1.0f / (1.0f + __expf(-x));
}
__device__ __forceinline__ void fma2(unsigned long long& acc,
                                     unsigned long long a,
                                     unsigned long long b) {
    asm("fma.rn.f32x2 %0, %1, %2, %0;" : "+l"(acc) : "l"(a), "l"(b));
}
__device__ __forceinline__ float sum2(unsigned long long v) {
    return __uint_as_float((unsigned)(v & 0xffffffffu)) +
           __uint_as_float((unsigned)(v >> 32));
}
__device__ __forceinline__ unsigned long long pack2(float a, float b) {
    unsigned long long r;
    asm("mov.b64 %0, {%1, %2};" : "=l"(r) : "f"(a), "f"(b));
    return r;
}

__global__ __launch_bounds__(THREADS, 1)
void mfvi_kernel(const float* __restrict__ s_span,
                 const float* __restrict__ s_pair,
                 float* __restrict__ out)
{
    __shared__ float sig[2][NN];

    const int s = blockIdx.x;
    const int t = threadIdx.x;
    const int w = t >> 5;
    const int l = t & 31;
    const int m = (s < 56) ? 11 : 10;          // tiles for this CTA

    // serpentine deal: byte-balanced across CTAs
    auto g_of = [&](int n) { return n * NSM + ((n & 1) ? (NSM - 1 - s) : s); };

    auto prefetch_tile = [&](int n) {
        if (n >= m) return;
        int g = g_of(n);
        int i = g >> 3;
        int R = NN - 1 - i;
        if (R <= 0) return;
        const char* p0 = (const char*)(s_pair
                         + (size_t)((g & 7) * NN + i) * (NN * NN)
                         + (size_t)(i + 1) * NN);
        int nl = R * 6;                        // 128B lines
        for (int x = t; x < nl; x += THREADS)
            asm volatile("prefetch.global.L2 [%0];" :: "l"(p0 + (size_t)x * 128));
    };

    const int j0  = w * RPW;                   // first row of my warp
    const int myj = j0 + l;                    // combine lane l<16 owns row myj

    #pragma unroll 1
    for (int n = 0; n < m; n++) {
        const int g  = g_of(n);
        const int i  = g >> 3;
        const int tz = (g & 7) * NN + i;
        const float* gP = s_pair + (size_t)tz * (NN * NN);

        // ---- load my register slice: row j0+u, cols l+32c (coalesced) ----
        unsigned long long val2[RPW][3];
        {
            const float* base = gP + (size_t)j0 * NN + l;
            #pragma unroll
            for (int u = 0; u < RPW; u++) {
                if (j0 + u > i) {
                    #pragma unroll
                    for (int p = 0; p < 3; p++) {
                        float a = __ldg(base + u * NN + p * 64);
                        float b = __ldg(base + u * NN + p * 64 + 32);
                        val2[u][p] = pack2(a, b);
                    }
                } else {
                    val2[u][0] = 0ull; val2[u][1] = 0ull; val2[u][2] = 0ull;
                }
            }
        }

        // ---- combine-lane setup: sigma^0 for all 192 rows + exclusion scalars ----
        float sv = 0.0f, ex_i = 0.0f, ex_j = 0.0f;
        if (l < RPW) {
            sv = s_span[(size_t)tz * NN + myj];
            float v = sigmoidf(sv);
            sig[0][myj] = v;
            if (myj <= i) {                     // constant rows: both buffers + out
                sig[1][myj] = v;
                out[(size_t)tz * NN + myj] = v;
            } else {
                ex_i = __ldg(gP + (size_t)myj * NN + i);    // P[j, i]
                ex_j = __ldg(gP + (size_t)myj * NN + myj);  // P[j, j]
            }
        }
        __syncthreads();                        // sigma^0 visible

        prefetch_tile(n + 1);                   // stream next tile into L2

        #pragma unroll
        for (int it = 0; it < 3; it++) {
            const float* sA = sig[(it == 1) ? 1 : 0];   // it0:0  it1:1  it2:0
            float*       sB = sig[(it == 0) ? 1 : 0];

            unsigned long long sg2[3];
            #pragma unroll
            for (int p = 0; p < 3; p++)
                sg2[p] = pack2(sA[l + p * 64], sA[l + p * 64 + 32]);

            float part[RPW];
            #pragma unroll
            for (int u = 0; u < RPW; u++) {
                unsigned long long acc = 0ull;
                fma2(acc, val2[u][0], sg2[0]);
                fma2(acc, val2[u][1], sg2[1]);
                fma2(acc, val2[u][2], sg2[2]);
                part[u] = sum2(acc);
            }
            // butterfly: after 5 rounds every lane holds every row's total
            #pragma unroll
            for (int o = 16; o >= 1; o >>= 1) {
                #pragma unroll
                for (int u = 0; u < RPW; u++)
                    part[u] += __shfl_xor_sync(0xffffffffu, part[u], o);
            }

            if (l < RPW && myj > i) {
                float q = sv + part[l] - sA[i] * ex_i - sA[myj] * ex_j;
                float v = sigmoidf(q);
                if (it < 2) sB[myj] = v;
                else        out[(size_t)tz * NN + myj] = v;
            }
            __syncthreads();                    // sB complete / sA reusable
        }
    }
}

extern "C" void kernel_launch(void* const* d_in, const int* in_sizes, int n_in,
                              void* d_out, int out_size)
{
    const float* s_span = (const float*)d_in[0];
    const float* s_pair = (const float*)d_in[1];
    float* out = (float*)d_out;

    mfvi_kernel<<<NSM, THREADS>>>(s_span, s_pair, out);
}

// round 16
// speedup vs baseline: 1.6205x; 1.6205x over previous
#include <cuda_runtime.h>
#include <cstdint>

// ConstituencyMFVI: B=8, N=192, 3 mean-field iterations.
// q[b,i,j] = s_span[b,i,j] + (j>i) * sum_{k != i, k != j} sigmoid(q[b,i,k]) * s_pair[b,i,j,k]
// out = sigmoid(q).
//
// R16 = R15 with the NaN fix: the dot/q update is guarded by (j > i) again
// (masked threads' r[]/SMEM rows are uninitialized; 0 * NaN poisoned q in R15).
//  - cross-wave L2 prefetch: CTA bid prefetches the tile of CTA bid+296 during
//    its compute phase -> that CTA's cp.asyncs hit L2, load phase shortens.
//  - fma.rn.f32x2 packed FMAs (half the FMA instructions per iteration).
// Everything else identical to R3 (35.6us): one CTA per (b,i), 192 threads,
// 2 CTAs/SM; low k-half in regs (24 x float4), high half in SMEM (stride 100);
// rows j<=i never loaded (113MB total HBM); exclusions zeroed in place.

namespace {
constexpr int NN      = 192;
constexpr int BB      = 8;
constexpr int HALF    = 96;
constexpr int PADH    = 100;   // half-row stride
constexpr int THREADS = 192;
constexpr int RCH     = 24;    // float4 chunks per half row
constexpr int NCONC   = 296;   // concurrent CTAs (2 per SM x 148)
constexpr int NTILES  = NN * BB;
}

__device__ __forceinline__ float sigmoidf(float x) {
    return 1.0f / (1.0f + __expf(-x));
}

union F4U {                     // float4 <-> 2 x f32x2 lanes
    float4 f;
    unsigned long long u[2];
};

__device__ __forceinline__ void fma2(unsigned long long& acc,
                                     unsigned long long a,
                                     unsigned long long b) {
    asm("fma.rn.f32x2 %0, %1, %2, %0;" : "+l"(acc) : "l"(a), "l"(b));
}
__device__ __forceinline__ float sum2(unsigned long long v) {
    return __uint_as_float((unsigned)(v & 0xffffffffu)) +
           __uint_as_float((unsigned)(v >> 32));
}

__global__ __launch_bounds__(THREADS, 2)
void mfvi_kernel(const float* __restrict__ s_span,
                 const float* __restrict__ s_pair,
                 float* __restrict__ out)
{
    extern __shared__ float sm[];
    float* buf = sm;               // [NN][PADH] : one k-half of rows (i,191]
    float* sig = sm + NN * PADH;   // [NN]

    const int i = blockIdx.x;
    const int b = blockIdx.y;
    const int j = threadIdx.x;
    const int R = NN - 1 - i;             // active rows (j > i)
    const int totChunks = R * RCH;        // 16B chunks per half-tile

    const size_t rowbase = (size_t)(b * NN + i);
    const float* gP = s_pair + rowbase * (size_t)(NN * NN);
    const float* gs = s_span + rowbase * NN;

    const uint32_t smemBuf = (uint32_t)__cvta_generic_to_shared(buf);

    // ---- phase 1: stream k in [0,96) of rows (i,191] into SMEM ----
    for (int g = j; g < totChunks; g += THREADS) {
        int row = i + 1 + g / RCH;
        int col = g - (g / RCH) * RCH;
        uint32_t dst = smemBuf + (uint32_t)(row * PADH + col * 4) * 4u;
        const float* src = gP + (size_t)row * NN + col * 4;
        asm volatile("cp.async.cg.shared.global [%0], [%1], 16;\n" :: "r"(dst), "l"(src));
    }
    asm volatile("cp.async.commit_group;\n");

    // overlap scalar setup with the inbound stream
    const float s = gs[j];
    float q = s;
    sig[j] = sigmoidf(q);                     // sigma^0

    asm volatile("cp.async.wait_group 0;\n");
    __syncthreads();

    // zero excluded low-half entries (k==i, k==j) in my own row, then cache to regs
    F4U r[RCH];
    if (j > i) {
        if (i < HALF) buf[j * PADH + i] = 0.0f;
        if (j < HALF) buf[j * PADH + j] = 0.0f;
        const float4* row4 = reinterpret_cast<const float4*>(buf + j * PADH);
        #pragma unroll
        for (int c = 0; c < RCH; c++) r[c].f = row4[c];
    }
    __syncthreads();   // all reg copies done before the buffer is overwritten

    // ---- phase 2: stream k in [96,192) into the same buffer ----
    for (int g = j; g < totChunks; g += THREADS) {
        int row = i + 1 + g / RCH;
        int col = g - (g / RCH) * RCH;
        uint32_t dst = smemBuf + (uint32_t)(row * PADH + col * 4) * 4u;
        const float* src = gP + (size_t)row * NN + HALF + col * 4;
        asm volatile("cp.async.cg.shared.global [%0], [%1], 16;\n" :: "r"(dst), "l"(src));
    }
    asm volatile("cp.async.commit_group;\n");
    asm volatile("cp.async.wait_group 0;\n");
    __syncthreads();

    // ---- compute phase begins: prefetch the tile two waves ahead into L2 ----
    {
        int nb = (b * NN + 0) * 0 + (blockIdx.y * NN + blockIdx.x) + NCONC; // bid + 296
        if (nb < NTILES) {
            int i2 = nb % NN;
            int b2 = nb / NN;
            int R2 = NN - 1 - i2;
            if (R2 > 0) {
                const char* p0 = (const char*)(s_pair
                                 + (size_t)(b2 * NN + i2) * (NN * NN)
                                 + (size_t)(i2 + 1) * NN);
                int nl = R2 * 6;               // 128B lines (768 B/row)
                for (int x = j; x < nl; x += THREADS)
                    asm volatile("prefetch.global.L2 [%0];" :: "l"(p0 + (size_t)x * 128));
            }
        }
    }

    // zero excluded high-half entries in my own row (own-row order, no barrier)
    if (j > i) {
        if (i >= HALF) buf[j * PADH + (i - HALF)] = 0.0f;
        if (j >= HALF) buf[j * PADH + (j - HALF)] = 0.0f;
    }

    const float4* row4 = reinterpret_cast<const float4*>(buf + j * PADH);
    const float4* sig4 = reinterpret_cast<const float4*>(sig);

    #pragma unroll 1
    for (int it = 0; it < 3; it++) {
        if (j > i) {                            // guard: masked rows hold garbage
            unsigned long long a0 = 0, a1 = 0, a2 = 0, a3 = 0;
            #pragma unroll
            for (int c = 0; c < RCH; c++) {
                F4U sg;  sg.f = sig4[c];        // low half: regs
                fma2(a0, r[c].u[0], sg.u[0]);
                fma2(a1, r[c].u[1], sg.u[1]);
                F4U p;   p.f  = row4[c];        // high half: SMEM
                F4U sg2; sg2.f = sig4[RCH + c];
                fma2(a2, p.u[0], sg2.u[0]);
                fma2(a3, p.u[1], sg2.u[1]);
            }
            q = s + ((sum2(a0) + sum2(a1)) + (sum2(a2) + sum2(a3)));
        }
        if (it < 2) {
            __syncthreads();                    // all dot reads done before sig update
            if (j > i) sig[j] = sigmoidf(q);    // masked sigma constant
            __syncthreads();
        }
    }

    out[rowbase * NN + j] = sigmoidf(q);
}

extern "C" void kernel_launch(void* const* d_in, const int* in_sizes, int n_in,
                              void* d_out, int out_size)
{
    const float* s_span = (const float*)d_in[0];
    const float* s_pair = (const float*)d_in[1];
    float* out = (float*)d_out;

    size_t smem = (size_t)(NN * PADH + NN) * sizeof(float);  // ~77.6 KB -> 2 CTAs/SM
    cudaFuncSetAttribute(mfvi_kernel,
                         cudaFuncAttributeMaxDynamicSharedMemorySize, (int)smem);

    dim3 grid(NN, BB);   // big tiles (small i) first
    mfvi_kernel<<<grid, THREADS, smem>>>(s_span, s_pair, out);
}

// round 17
// speedup vs baseline: 1.6741x; 1.0331x over previous
#include <cuda_runtime.h>
#include <cstdint>

// ConstituencyMFVI: B=8, N=192, 3 mean-field iterations.
// q[b,i,j] = s_span[b,i,j] + (j>i) * sum_{k != i, k != j} sigmoid(q[b,i,k]) * s_pair[b,i,j,k]
// out = sigmoid(q).
//
// R17 = R16 base (one CTA per (b,i), 192 threads, 2 CTAs/SM, low k-half in
// regs, high half in SMEM, fma.rn.f32x2, analytic mask, 113MB HBM) plus:
//  - ANTI-PHASE STAGGER: the second-slot CTAs of wave 1 (bid in [148,296))
//    spin ~3000 cycles before loading, so each SM's two CTAs alternate
//    load/compute phases instead of running lockstep -> DRAM stays busy
//    during compute. Later CTAs inherit the offset from staggered frees.
//  - double-buffered sigma: read bufA / write bufB / ONE barrier per
//    iteration (was 2), no read-write hazard.
//  (cross-wave L2 prefetch removed: measured inert.)

namespace {
constexpr int NN      = 192;
constexpr int BB      = 8;
constexpr int HALF    = 96;
constexpr int PADH    = 100;   // half-row stride
constexpr int THREADS = 192;
constexpr int RCH     = 24;    // float4 chunks per half row
constexpr long long STAGGER_CYC = 3000;
}

__device__ __forceinline__ float sigmoidf(float x) {
    return 1.0f / (1.0f + __expf(-x));
}

union F4U {                     // float4 <-> 2 x f32x2 lanes
    float4 f;
    unsigned long long u[2];
};

__device__ __forceinline__ void fma2(unsigned long long& acc,
                                     unsigned long long a,
                                     unsigned long long b) {
    asm("fma.rn.f32x2 %0, %1, %2, %0;" : "+l"(acc) : "l"(a), "l"(b));
}
__device__ __forceinline__ float sum2(unsigned long long v) {
    return __uint_as_float((unsigned)(v & 0xffffffffu)) +
           __uint_as_float((unsigned)(v >> 32));
}

__global__ __launch_bounds__(THREADS, 2)
void mfvi_kernel(const float* __restrict__ s_span,
                 const float* __restrict__ s_pair,
                 float* __restrict__ out)
{
    extern __shared__ float sm[];
    float* buf  = sm;                    // [NN][PADH] : one k-half of rows (i,191]
    float* sig0 = sm + NN * PADH;        // [NN]
    float* sig1 = sig0 + NN;             // [NN]

    const int i = blockIdx.x;
    const int b = blockIdx.y;
    const int j = threadIdx.x;
    const int bid = b * NN + i;          // launch-order block id (x fastest)

    // anti-phase stagger: second-slot CTAs of wave 1 delay ~half a tile period
    if (bid >= 148 && bid < 296) {
        long long t0 = clock64();
        while (clock64() - t0 < STAGGER_CYC) { }
    }

    const int R = NN - 1 - i;            // active rows (j > i)
    const int totChunks = R * RCH;       // 16B chunks per half-tile

    const size_t rowbase = (size_t)bid;
    const float* gP = s_pair + rowbase * (size_t)(NN * NN);
    const float* gs = s_span + rowbase * NN;

    const uint32_t smemBuf = (uint32_t)__cvta_generic_to_shared(buf);

    // ---- phase 1: stream k in [0,96) of rows (i,191] into SMEM ----
    for (int g = j; g < totChunks; g += THREADS) {
        int row = i + 1 + g / RCH;
        int col = g - (g / RCH) * RCH;
        uint32_t dst = smemBuf + (uint32_t)(row * PADH + col * 4) * 4u;
        const float* src = gP + (size_t)row * NN + col * 4;
        asm volatile("cp.async.cg.shared.global [%0], [%1], 16;\n" :: "r"(dst), "l"(src));
    }
    asm volatile("cp.async.commit_group;\n");

    // overlap scalar setup with the inbound stream
    const float s = gs[j];
    float q = s;
    {
        float v = sigmoidf(s);
        sig0[j] = v;                     // sigma^0 for all rows
        if (j <= i) sig1[j] = v;         // constant rows pre-seeded in BOTH buffers
    }

    asm volatile("cp.async.wait_group 0;\n");
    __syncthreads();

    // zero excluded low-half entries (k==i, k==j) in my own row, then cache to regs
    F4U r[RCH];
    if (j > i) {
        if (i < HALF) buf[j * PADH + i] = 0.0f;
        if (j < HALF) buf[j * PADH + j] = 0.0f;
        const float4* row4 = reinterpret_cast<const float4*>(buf + j * PADH);
        #pragma unroll
        for (int c = 0; c < RCH; c++) r[c].f = row4[c];
    }
    __syncthreads();   // all reg copies done before the buffer is overwritten

    // ---- phase 2: stream k in [96,192) into the same buffer ----
    for (int g = j; g < totChunks; g += THREADS) {
        int row = i + 1 + g / RCH;
        int col = g - (g / RCH) * RCH;
        uint32_t dst = smemBuf + (uint32_t)(row * PADH + col * 4) * 4u;
        const float* src = gP + (size_t)row * NN + HALF + col * 4;
        asm volatile("cp.async.cg.shared.global [%0], [%1], 16;\n" :: "r"(dst), "l"(src));
    }
    asm volatile("cp.async.commit_group;\n");
    asm volatile("cp.async.wait_group 0;\n");
    __syncthreads();

    // zero excluded high-half entries in my own row (own-row order, no barrier)
    if (j > i) {
        if (i >= HALF) buf[j * PADH + (i - HALF)] = 0.0f;
        if (j >= HALF) buf[j * PADH + (j - HALF)] = 0.0f;
    }

    const float4* row4 = reinterpret_cast<const float4*>(buf + j * PADH);

    #pragma unroll 1
    for (int it = 0; it < 3; it++) {
        const float4* sigA = reinterpret_cast<const float4*>((it == 1) ? sig1 : sig0);
        float*        sigB = (it == 0) ? sig1 : sig0;

        if (j > i) {
            unsigned long long a0 = 0, a1 = 0, a2 = 0, a3 = 0;
            #pragma unroll
            for (int c = 0; c < RCH; c++) {
                F4U sg;  sg.f = sigA[c];        // low half: regs
                fma2(a0, r[c].u[0], sg.u[0]);
                fma2(a1, r[c].u[1], sg.u[1]);
                F4U p;   p.f  = row4[c];        // high half: SMEM
                F4U sg2; sg2.f = sigA[RCH + c];
                fma2(a2, p.u[0], sg2.u[0]);
                fma2(a3, p.u[1], sg2.u[1]);
            }
            q = s + ((sum2(a0) + sum2(a1)) + (sum2(a2) + sum2(a3)));
        }
        if (it < 2) {
            if (j > i) sigB[j] = sigmoidf(q);   // write buffer != read buffer
            __syncthreads();                    // one barrier per iteration
        }
    }

    out[rowbase * NN + j] = sigmoidf(q);
}

extern "C" void kernel_launch(void* const* d_in, const int* in_sizes, int n_in,
                              void* d_out, int out_size)
{
    const float* s_span = (const float*)d_in[0];
    const float* s_pair = (const float*)d_in[1];
    float* out = (float*)d_out;

    size_t smem = (size_t)(NN * PADH + 2 * NN) * sizeof(float);  // ~78.3 KB -> 2 CTAs/SM
    cudaFuncSetAttribute(mfvi_kernel,
                         cudaFuncAttributeMaxDynamicSharedMemorySize, (int)smem);

    dim3 grid(NN, BB);   // big tiles (small i) first
    mfvi_kernel<<<grid, THREADS, smem>>>(s_span, s_pair, out);
}